// round 12
// baseline (speedup 1.0000x reference)
#include <cuda_runtime.h>
#include <cuda_fp16.h>
#include <math.h>
#include <stdint.h>

#define BS    8
#define C     128
#define CH    64
#define NTOK  4096
#define TQ    64        // queries per CTA (4 warps x 16 rows)
#define TK    64
#define KTILES (NTOK/TK)
#define RS    72        // smem row stride in fp16 elems (144B)

// ---------------------------------------------------------------------------
// Static scratch
// ---------------------------------------------------------------------------
__device__ __half g_Khi[(size_t)BS * NTOK * CH];  // [b][n][d]
__device__ __half g_Klo[(size_t)BS * NTOK * CH];
__device__ __half g_Vhi[(size_t)BS * C * NTOK];   // [b][c][n]
__device__ __half g_Wh [C * C];                   // W_out hi  [co][ci]
__device__ __half g_Wl [C * C];
__device__ __half g_WtH[CH * C];                  // W_tgt hi
__device__ __half g_WtL[CH * C];
__device__ __half g_WrH[CH * C];                  // W_ref hi
__device__ __half g_WrL[CH * C];

// ---------------------------------------------------------------------------
// PTX helpers (baseline ISA)
// ---------------------------------------------------------------------------
__device__ __forceinline__ uint32_t smem_u32(const void* p) {
    uint32_t a;
    asm("{ .reg .u64 t; cvta.to.shared.u64 t, %1; cvt.u32.u64 %0, t; }"
        : "=r"(a) : "l"(p));
    return a;
}
__device__ __forceinline__ void ldsm4(uint32_t* r, uint32_t a) {
    asm volatile("ldmatrix.sync.aligned.m8n8.x4.shared.b16 {%0,%1,%2,%3}, [%4];"
        : "=r"(r[0]), "=r"(r[1]), "=r"(r[2]), "=r"(r[3]) : "r"(a));
}
__device__ __forceinline__ void mma_f16(float* d, const uint32_t* a, const uint32_t* b) {
    asm volatile("mma.sync.aligned.m16n8k16.row.col.f32.f16.f16.f32 "
        "{%0,%1,%2,%3},{%4,%5,%6,%7},{%8,%9},{%0,%1,%2,%3};"
        : "+f"(d[0]), "+f"(d[1]), "+f"(d[2]), "+f"(d[3])
        : "r"(a[0]), "r"(a[1]), "r"(a[2]), "r"(a[3]), "r"(b[0]), "r"(b[1]));
}
__device__ __forceinline__ uint32_t cvt2h(float hi, float lo) {
    uint32_t r;
    asm("cvt.rn.f16x2.f32 %0, %1, %2;" : "=r"(r) : "f"(hi), "f"(lo));
    return r;
}
__device__ __forceinline__ uint32_t ex2h2(uint32_t x) {
    uint32_t r;
    asm("ex2.approx.f16x2 %0, %1;" : "=r"(r) : "r"(x));
    return r;
}
__device__ __forceinline__ void cpa16(uint32_t dst, const void* src) {
    asm volatile("cp.async.cg.shared.global [%0], [%1], 16;" :: "r"(dst), "l"(src));
}
#define CP_COMMIT() asm volatile("cp.async.commit_group;" ::: "memory")
#define CP_WAIT1()  asm volatile("cp.async.wait_group 1;" ::: "memory")
#define CP_WAIT0()  asm volatile("cp.async.wait_group 0;" ::: "memory")

// ---------------------------------------------------------------------------
// All weight splits in one kernel
// ---------------------------------------------------------------------------
__global__ __launch_bounds__(256)
void split_all(const float* __restrict__ Wt, const float* __restrict__ Wr,
               const float* __restrict__ Wo,
               __half* __restrict__ wth, __half* __restrict__ wtl,
               __half* __restrict__ wrh, __half* __restrict__ wrl,
               __half* __restrict__ wh,  __half* __restrict__ wl)
{
    int i = blockIdx.x * 256 + threadIdx.x;
    const float* src; __half *dh, *dl; int j;
    if (i < 8192)        { src = Wt; dh = wth; dl = wtl; j = i; }
    else if (i < 16384)  { src = Wr; dh = wrh; dl = wrl; j = i - 8192; }
    else                 { src = Wo; dh = wh;  dl = wl;  j = i - 16384; }
    float x = src[j];
    __half hh = __float2half_rn(x);
    dh[j] = hh;
    dl[j] = __float2half_rn(x - __half2float(hh));
}

// ---------------------------------------------------------------------------
// Convert V (= ref, [b][c][n]) to fp16
// ---------------------------------------------------------------------------
__global__ __launch_bounds__(256)
void conv_v(const float* __restrict__ ref, __half* __restrict__ vhi)
{
    size_t i = ((size_t)blockIdx.x * 256 + threadIdx.x) * 8;
    float4 a = *(const float4*)(ref + i);
    float4 b = *(const float4*)(ref + i + 4);
    float v[8] = {a.x, a.y, a.z, a.w, b.x, b.y, b.z, b.w};
    __align__(16) __half h[8];
#pragma unroll
    for (int j = 0; j < 8; j++) h[j] = __float2half_rn(v[j]);
    *(uint4*)(vhi + i) = *(const uint4*)h;
}

// ---------------------------------------------------------------------------
// Shared projection core for 128-thread CTAs, 64-token tiles.
// smem: WH[64][72], WL[64][72], TH[64][72], TL[64][72]  (36864 B)
// ---------------------------------------------------------------------------
#define PR_WH 0
#define PR_WL 9216
#define PR_TH 18432
#define PR_TL 27648
#define PR_SZ 36864

template<typename SM>
__device__ __forceinline__ void proj_half(
    SM* smc, uint32_t sb, int half,
    const float* __restrict__ xb,
    const __half* __restrict__ WH, const __half* __restrict__ WL,
    int tid, int wid, int lane, int rbase, float acc[8][4])
{
    const int lg  = lane >> 3, ln8 = lane & 7;
    const __half* whp = WH + half * 64;
    const __half* wlp = WL + half * 64;
    for (int i = tid; i < 512; i += 128) {
        int r = i >> 3, j = i & 7;
        *(uint4*)((char*)smc + PR_WH + r * 144 + j * 16) = *(const uint4*)(whp + r * 128 + j * 8);
        *(uint4*)((char*)smc + PR_WL + r * 144 + j * 16) = *(const uint4*)(wlp + r * 128 + j * 8);
    }
#pragma unroll
    for (int i = 0; i < 16; i++) {
        int tok = lane + 32 * (i & 1);
        int cp  = wid + 4 * (i >> 1);
        int c   = half * 64 + cp * 2;
        float x0 = xb[(size_t)c * NTOK + tok];
        float x1 = xb[(size_t)(c + 1) * NTOK + tok];
        __half h0 = __float2half_rn(x0), h1 = __float2half_rn(x1);
        __half l0 = __float2half_rn(x0 - __half2float(h0));
        __half l1 = __float2half_rn(x1 - __half2float(h1));
        *(__half2*)((char*)smc + PR_TH + tok * 144 + cp * 4) = __halves2half2(h0, h1);
        *(__half2*)((char*)smc + PR_TL + tok * 144 + cp * 4) = __halves2half2(l0, l1);
    }
    __syncthreads();

    uint32_t ah[4][4], al[4][4];
    {
        const int ar = rbase + (lane & 15);
        const int ac = 8 * (lane >> 4);
#pragma unroll
        for (int kk = 0; kk < 4; kk++) {
            uint32_t off = (uint32_t)(ar * RS + kk * 16 + ac) * 2;
            ldsm4(ah[kk], sb + PR_TH + off);
            ldsm4(al[kk], sb + PR_TL + off);
        }
    }
#pragma unroll
    for (int jn = 0; jn < 8; jn++) {
        uint32_t bh01[4], bh23[4], bl01[4], bl23[4];
        uint32_t wa = sb + PR_WH + (uint32_t)((jn * 8 + ln8) * RS + lg * 8) * 2;
        ldsm4(bh01, wa);
        ldsm4(bh23, wa + 64);
        ldsm4(bl01, wa + (PR_WL - PR_WH));
        ldsm4(bl23, wa + (PR_WL - PR_WH) + 64);
        mma_f16(acc[jn], ah[0], bh01);  mma_f16(acc[jn], ah[1], bh01 + 2);
        mma_f16(acc[jn], ah[2], bh23);  mma_f16(acc[jn], ah[3], bh23 + 2);
        mma_f16(acc[jn], ah[0], bl01);  mma_f16(acc[jn], ah[1], bl01 + 2);
        mma_f16(acc[jn], ah[2], bl23);  mma_f16(acc[jn], ah[3], bl23 + 2);
        mma_f16(acc[jn], al[0], bh01);  mma_f16(acc[jn], al[1], bh01 + 2);
        mma_f16(acc[jn], al[2], bh23);  mma_f16(acc[jn], al[3], bh23 + 2);
    }
    __syncthreads();
}

// ---------------------------------------------------------------------------
// K projection (tensor-core), 128 threads / 64 tokens, token-major output
// ---------------------------------------------------------------------------
__global__ __launch_bounds__(128)
void proj_k_tc(const float* __restrict__ ref,
               const __half* __restrict__ WrH, const __half* __restrict__ WrL,
               const float* __restrict__ b_ref,
               __half* __restrict__ khi, __half* __restrict__ klo)
{
    extern __shared__ __align__(16) char smk[];
    const uint32_t sb = smem_u32(smk);
    const int tid = threadIdx.x, wid = tid >> 5, lane = tid & 31;
    const int b = blockIdx.y, n0 = blockIdx.x * 64;
    const int rbase = wid * 16;
    const int col0 = 2 * (lane & 3);

    float acc[8][4];
#pragma unroll
    for (int jn = 0; jn < 8; jn++) {
        float2 bb = *(const float2*)&b_ref[jn * 8 + col0];
        acc[jn][0] = bb.x; acc[jn][1] = bb.y;
        acc[jn][2] = bb.x; acc[jn][3] = bb.y;
    }
    const float* xb = ref + (size_t)b * C * NTOK + n0;
#pragma unroll 1
    for (int half = 0; half < 2; half++)
        proj_half(smk, sb, half, xb, WrH, WrL, tid, wid, lane, rbase, acc);

    const int r0 = rbase + (lane >> 2);
#pragma unroll
    for (int jn = 0; jn < 8; jn++) {
        int col = jn * 8 + col0;
        float v0 = fmaxf(acc[jn][0], 0.f), v1 = fmaxf(acc[jn][1], 0.f);
        float v2 = fmaxf(acc[jn][2], 0.f), v3 = fmaxf(acc[jn][3], 0.f);
        __half h0 = __float2half_rn(v0), h1 = __float2half_rn(v1);
        __half h2 = __float2half_rn(v2), h3 = __float2half_rn(v3);
        size_t i0 = ((size_t)b * NTOK + n0 + r0) * CH + col;
        size_t i1 = ((size_t)b * NTOK + n0 + r0 + 8) * CH + col;
        *(__half2*)&khi[i0] = __halves2half2(h0, h1);
        *(__half2*)&khi[i1] = __halves2half2(h2, h3);
        *(__half2*)&klo[i0] = __halves2half2(__float2half_rn(v0 - __half2float(h0)),
                                             __float2half_rn(v1 - __half2float(h1)));
        *(__half2*)&klo[i1] = __halves2half2(__float2half_rn(v2 - __half2float(h2)),
                                             __float2half_rn(v3 - __half2float(h3)));
    }
}

// ---------------------------------------------------------------------------
// Flash attention: 128 threads, __launch_bounds__(128,3) -> 3 CTAs/SM target.
// SMEM: 2 x { KH[64][72] KL[64][72] VH[128][72] } = 73728 B
// Epilogue: gate GEMM jn-blocked (64 output channels at a time), regions
//   EP_WH/EP_WL/EP_TH/EP_TL each 9216 B (total 36864 <= 73728). O stays in
//   registers (normalized in place); g block is only 32 regs.
// ---------------------------------------------------------------------------
#define OFF_KH 0
#define OFF_KL 9216
#define OFF_VH 18432
#define BUF    36864
#define SMEM_ATTN (2 * BUF)
#define EP_WH  0
#define EP_WL  9216
#define EP_TH  18432
#define EP_TL  27648

__global__ __launch_bounds__(128, 3)
void attn_mma(const __half* __restrict__ WtH, const __half* __restrict__ WtL,
              const float* __restrict__ b_tgt,
              const __half* __restrict__ Khi, const __half* __restrict__ Klo,
              const __half* __restrict__ Vhi,
              const __half* __restrict__ Wh,  const __half* __restrict__ Wl,
              const float* __restrict__ tgt,  const float* __restrict__ b_out,
              float* __restrict__ out)
{
    extern __shared__ __align__(16) char smc[];
    const uint32_t sb = smem_u32(smc);

    const int tid   = threadIdx.x;
    const int wid   = tid >> 5, lane = tid & 31;
    const int b     = blockIdx.y;
    const int n0    = blockIdx.x * TQ;
    const int rbase = wid * 16;
    const int lg    = lane >> 3;
    const int ln8   = lane & 7;
    const int lgr   = (lg >> 1) * 8 + ln8;
    const int lko   = 8 * (lg & 1);
    const int col0  = 2 * (lane & 3);

    const float* tb = tgt + (size_t)b * C * NTOK + n0;

    // ======== fused Q projection ========
    uint32_t qa[4][4], qb[4][4];
    {
        float qacc[8][4];
#pragma unroll
        for (int jn = 0; jn < 8; jn++) {
            float2 bb = *(const float2*)&b_tgt[jn * 8 + col0];
            qacc[jn][0] = bb.x; qacc[jn][1] = bb.y;
            qacc[jn][2] = bb.x; qacc[jn][3] = bb.y;
        }
#pragma unroll 1
        for (int half = 0; half < 2; half++)
            proj_half(smc, sb, half, tb, WtH, WtL, tid, wid, lane, rbase, qacc);

#pragma unroll
        for (int kk = 0; kk < 4; kk++) {
#pragma unroll
            for (int hh = 0; hh < 2; hh++) {
                int j = 2 * kk + hh;
                float v0 = fmaxf(qacc[j][0], 0.f), v1 = fmaxf(qacc[j][1], 0.f);
                float v2 = fmaxf(qacc[j][2], 0.f), v3 = fmaxf(qacc[j][3], 0.f);
                uint32_t h01 = cvt2h(v1, v0), h23 = cvt2h(v3, v2);
                float2 f01 = __half22float2(*(__half2*)&h01);
                float2 f23 = __half22float2(*(__half2*)&h23);
                qa[kk][2 * hh]     = h01;
                qa[kk][2 * hh + 1] = h23;
                qb[kk][2 * hh]     = cvt2h(v1 - f01.y, v0 - f01.x);
                qb[kk][2 * hh + 1] = cvt2h(v3 - f23.y, v2 - f23.x);
            }
        }
    }

    // ======== main loop ========
    const __half* KHb = Khi + (size_t)b * NTOK * CH;
    const __half* KLb = Klo + (size_t)b * NTOK * CH;
    const __half* VHb = Vhi + (size_t)b * C * NTOK;
    auto prefetch = [&](int t, int bsel) {
        uint32_t base = sb + (uint32_t)bsel * BUF;
        const __half* khp = KHb + (size_t)t * TK * CH;
        const __half* klp = KLb + (size_t)t * TK * CH;
        for (int i = tid; i < 512; i += 128) {
            int r = i >> 3, j = i & 7;
            uint32_t d = base + r * 144 + j * 16;
            cpa16(d + OFF_KH, khp + r * 64 + j * 8);
            cpa16(d + OFF_KL, klp + r * 64 + j * 8);
        }
        const __half* vhp = VHb + t * TK;
        for (int i = tid; i < 1024; i += 128) {
            int c = i >> 3, j = i & 7;
            cpa16(base + OFF_VH + c * 144 + j * 16, vhp + (size_t)c * NTOK + j * 8);
        }
    };

    float o[16][4];
#pragma unroll
    for (int jn = 0; jn < 16; jn++)
#pragma unroll
        for (int e = 0; e < 4; e++) o[jn][e] = 0.0f;
    float osum[4] = {0.f, 0.f, 0.f, 0.f};
    float mx0 = -1e30f, mx1 = -1e30f;

    const uint32_t ones2[2] = {0x3C003C00u, 0x3C003C00u};
    const float L2E = 1.4426950408889634f;

    prefetch(0, 0);
    CP_COMMIT();

    for (int t = 0; t < KTILES; t++) {
        __syncthreads();
        if (t + 1 < KTILES) prefetch(t + 1, (t + 1) & 1);
        CP_COMMIT();
        CP_WAIT1();
        __syncthreads();
        const uint32_t base = sb + (uint32_t)(t & 1) * BUF;

        // ---- S = Q.K^T, 3-term fp16 ----
        float s[8][4];
#pragma unroll
        for (int j = 0; j < 8; j++)
#pragma unroll
            for (int e = 0; e < 4; e++) s[j][e] = 0.0f;

#pragma unroll
        for (int kk = 0; kk < 4; kk++) {
#pragma unroll
            for (int jp = 0; jp < 4; jp++) {
                uint32_t kh4[4], kl4[4];
                uint32_t ka = base + OFF_KH +
                    (uint32_t)((jp * 16 + lgr) * RS + kk * 16 + lko) * 2;
                ldsm4(kh4, ka);
                ldsm4(kl4, ka + (OFF_KL - OFF_KH));
                mma_f16(s[2 * jp],     qa[kk], kh4);
                mma_f16(s[2 * jp + 1], qa[kk], kh4 + 2);
                mma_f16(s[2 * jp],     qa[kk], kl4);
                mma_f16(s[2 * jp + 1], qa[kk], kl4 + 2);
                mma_f16(s[2 * jp],     qb[kk], kh4);
                mma_f16(s[2 * jp + 1], qb[kk], kh4 + 2);
            }
        }

        // ---- online softmax (max + rescale) ----
        float a0 = -1e30f, a1 = -1e30f;
#pragma unroll
        for (int j = 0; j < 8; j++) {
            a0 = fmaxf(a0, fmaxf(s[j][0], s[j][1]));
            a1 = fmaxf(a1, fmaxf(s[j][2], s[j][3]));
        }
        a0 = fmaxf(a0, __shfl_xor_sync(0xffffffffu, a0, 1));
        a0 = fmaxf(a0, __shfl_xor_sync(0xffffffffu, a0, 2));
        a1 = fmaxf(a1, __shfl_xor_sync(0xffffffffu, a1, 1));
        a1 = fmaxf(a1, __shfl_xor_sync(0xffffffffu, a1, 2));
        float mn0 = fmaxf(mx0, a0), mn1 = fmaxf(mx1, a1);
        if (__any_sync(0xffffffffu, (mn0 > mx0) || (mn1 > mx1))) {
            float cr0 = __expf(mx0 - mn0), cr1 = __expf(mx1 - mn1);
#pragma unroll
            for (int jn = 0; jn < 16; jn++) {
                o[jn][0] *= cr0; o[jn][1] *= cr0;
                o[jn][2] *= cr1; o[jn][3] *= cr1;
            }
            osum[0] *= cr0; osum[1] *= cr0;
            osum[2] *= cr1; osum[3] *= cr1;
        }
        mx0 = mn0; mx1 = mn1;

        // ---- per-kk: exp (4 regs live) then AV ----
        const float mL0 = mn0 * L2E, mL1 = mn1 * L2E;
#pragma unroll
        for (int kk = 0; kk < 4; kk++) {
            int j0 = 2 * kk, j1 = 2 * kk + 1;
            uint32_t ph[4];
            ph[0] = ex2h2(cvt2h(fmaf(s[j0][1], L2E, -mL0),
                                fmaf(s[j0][0], L2E, -mL0)));
            ph[1] = ex2h2(cvt2h(fmaf(s[j0][3], L2E, -mL1),
                                fmaf(s[j0][2], L2E, -mL1)));
            ph[2] = ex2h2(cvt2h(fmaf(s[j1][1], L2E, -mL0),
                                fmaf(s[j1][0], L2E, -mL0)));
            ph[3] = ex2h2(cvt2h(fmaf(s[j1][3], L2E, -mL1),
                                fmaf(s[j1][2], L2E, -mL1)));
            mma_f16(osum, ph, ones2);
#pragma unroll
            for (int jp = 0; jp < 8; jp++) {
                uint32_t vh4[4];
                uint32_t va = base + OFF_VH +
                    (uint32_t)((jp * 16 + lgr) * RS + kk * 16 + lko) * 2;
                ldsm4(vh4, va);
                mma_f16(o[2 * jp],     ph, vh4);
                mma_f16(o[2 * jp + 1], ph, vh4 + 2);
            }
        }
    }

    // ======== epilogue: normalize O in registers ========
    CP_WAIT0();
    {
        const float inv0 = 1.0f / osum[0], inv1 = 1.0f / osum[2];
#pragma unroll
        for (int jn = 0; jn < 16; jn++) {
            o[jn][0] *= inv0; o[jn][1] *= inv0;
            o[jn][2] *= inv1; o[jn][3] *= inv1;
        }
    }

    // ======== gate GEMM, jn-blocked (64 output channels per block) ========
    const int trow = rbase + (lane >> 2);
#pragma unroll 1
    for (int jnb = 0; jnb < 2; jnb++) {
        float g[8][4];
#pragma unroll
        for (int jn = 0; jn < 8; jn++) {
            float ba = b_out[jnb * 64 + jn * 8 + col0];
            float bb = b_out[jnb * 64 + jn * 8 + col0 + 1];
            g[jn][0] = ba; g[jn][1] = bb; g[jn][2] = ba; g[jn][3] = bb;
        }

#pragma unroll 1
        for (int half = 0; half < 2; half++) {
            __syncthreads();  // previous block's reads / loop reads done
            // stage W rows jnb*64..+63, input cols half*64..+63 (hi & lo)
            const __half* whp = Wh + (size_t)(jnb * 64) * 128 + half * 64;
            const __half* wlp = Wl + (size_t)(jnb * 64) * 128 + half * 64;
            for (int i = tid; i < 512; i += 128) {
                int r = i >> 3, j = i & 7;
                *(uint4*)(smc + EP_WH + r * 144 + j * 16) = *(const uint4*)(whp + r * 128 + j * 8);
                *(uint4*)(smc + EP_WL + r * 144 + j * 16) = *(const uint4*)(wlp + r * 128 + j * 8);
            }
            // stage tgt tile (64 tokens, channels half*64..+63, split hi/lo)
#pragma unroll
            for (int i = 0; i < 16; i++) {
                int tok = lane + 32 * (i & 1);
                int cp  = wid + 4 * (i >> 1);
                int c   = half * 64 + cp * 2;
                float x0 = tb[(size_t)c * NTOK + tok];
                float x1 = tb[(size_t)(c + 1) * NTOK + tok];
                __half h0 = __float2half_rn(x0), h1 = __float2half_rn(x1);
                __half l0 = __float2half_rn(x0 - __half2float(h0));
                __half l1 = __float2half_rn(x1 - __half2float(h1));
                *(__half2*)(smc + EP_TH + tok * 144 + cp * 4) = __halves2half2(h0, h1);
                *(__half2*)(smc + EP_TL + tok * 144 + cp * 4) = __halves2half2(l0, l1);
            }
            __syncthreads();

            uint32_t ah[4][4], al[4][4];
            {
                const int ar = rbase + (lane & 15);
                const int ac = 8 * (lane >> 4);
#pragma unroll
                for (int kk = 0; kk < 4; kk++) {
                    uint32_t off = (uint32_t)(ar * RS + kk * 16 + ac) * 2;
                    ldsm4(ah[kk], sb + EP_TH + off);
                    ldsm4(al[kk], sb + EP_TL + off);
                }
            }
#pragma unroll
            for (int jn = 0; jn < 8; jn++) {
                uint32_t bh01[4], bh23[4], bl01[4], bl23[4];
                uint32_t wa = sb + EP_WH + (uint32_t)((jn * 8 + ln8) * RS + lg * 8) * 2;
                ldsm4(bh01, wa);
                ldsm4(bh23, wa + 64);
                ldsm4(bl01, wa + (EP_WL - EP_WH));
                ldsm4(bl23, wa + (EP_WL - EP_WH) + 64);
                mma_f16(g[jn], ah[0], bh01);  mma_f16(g[jn], ah[1], bh01 + 2);
                mma_f16(g[jn], ah[2], bh23);  mma_f16(g[jn], ah[3], bh23 + 2);
                mma_f16(g[jn], ah[0], bl01);  mma_f16(g[jn], ah[1], bl01 + 2);
                mma_f16(g[jn], ah[2], bl23);  mma_f16(g[jn], ah[3], bl23 + 2);
                mma_f16(g[jn], al[0], bh01);  mma_f16(g[jn], al[1], bh01 + 2);
                mma_f16(g[jn], al[2], bh23);  mma_f16(g[jn], al[3], bh23 + 2);
            }
        }

        // gate + store this block's 64 channels
#pragma unroll
        for (int jn = 0; jn < 8; jn++) {
            int c = jnb * 64 + jn * 8 + col0;
            const float* oj = o[jnb * 8 + jn];
            size_t gi = ((size_t)b * C + c) * NTOK + n0 + trow;
            out[gi]            = oj[0] * g[jn][0];
            out[gi + NTOK]     = oj[1] * g[jn][1];
            out[gi + 8]        = oj[2] * g[jn][2];
            out[gi + NTOK + 8] = oj[3] * g[jn][3];
        }
    }
}

// ---------------------------------------------------------------------------
extern "C" void kernel_launch(void* const* d_in, const int* in_sizes, int n_in,
                              void* d_out, int out_size)
{
    const float* tgt   = (const float*)d_in[0];
    const float* refp  = (const float*)d_in[1];
    const float* W_tgt = (const float*)d_in[2];
    const float* b_tgt = (const float*)d_in[3];
    const float* W_ref = (const float*)d_in[4];
    const float* b_ref = (const float*)d_in[5];
    const float* W_out = (const float*)d_in[6];
    const float* b_out = (const float*)d_in[7];
    float* out = (float*)d_out;

    __half *kh, *kl, *vh, *wh, *wl, *wth, *wtl, *wrh, *wrl;
    cudaGetSymbolAddress((void**)&kh,  g_Khi);
    cudaGetSymbolAddress((void**)&kl,  g_Klo);
    cudaGetSymbolAddress((void**)&vh,  g_Vhi);
    cudaGetSymbolAddress((void**)&wh,  g_Wh);
    cudaGetSymbolAddress((void**)&wl,  g_Wl);
    cudaGetSymbolAddress((void**)&wth, g_WtH);
    cudaGetSymbolAddress((void**)&wtl, g_WtL);
    cudaGetSymbolAddress((void**)&wrh, g_WrH);
    cudaGetSymbolAddress((void**)&wrl, g_WrL);

    cudaFuncSetAttribute(proj_k_tc, cudaFuncAttributeMaxDynamicSharedMemorySize, PR_SZ);
    cudaFuncSetAttribute(attn_mma,  cudaFuncAttributeMaxDynamicSharedMemorySize, SMEM_ATTN);

    split_all<<<(2 * CH * C + C * C) / 256, 256>>>(
        W_tgt, W_ref, W_out, wth, wtl, wrh, wrl, wh, wl);
    conv_v<<<(BS * C * NTOK) / (256 * 8), 256>>>(refp, vh);
    proj_k_tc<<<dim3(NTOK / 64, BS), 128, PR_SZ>>>(refp, wrh, wrl, b_ref, kh, kl);

    attn_mma<<<dim3(NTOK / TQ, BS), 128, SMEM_ATTN>>>(
        wth, wtl, b_tgt, kh, kl, vh, wh, wl, tgt, b_out, out);
}

// round 13
// speedup vs baseline: 1.6040x; 1.6040x over previous
#include <cuda_runtime.h>
#include <cuda_fp16.h>
#include <math.h>
#include <stdint.h>

#define BS    8
#define C     128
#define CH    64
#define NTOK  4096
#define TQ    64        // queries per CTA (4 warps x 16 rows)
#define TK    64
#define KTILES (NTOK/TK)
#define RS    72        // smem row stride in fp16 elems (144B)

// ---------------------------------------------------------------------------
// Static scratch
// ---------------------------------------------------------------------------
__device__ __half g_Khi[(size_t)BS * NTOK * CH];  // [b][n][d]
__device__ __half g_Klo[(size_t)BS * NTOK * CH];
__device__ __half g_Vhi[(size_t)BS * C * NTOK];   // [b][c][n]
__device__ __half g_Wh [C * C];                   // W_out hi  [co][ci]
__device__ __half g_Wl [C * C];
__device__ __half g_WtH[CH * C];                  // W_tgt hi
__device__ __half g_WtL[CH * C];
__device__ __half g_WrH[CH * C];                  // W_ref hi
__device__ __half g_WrL[CH * C];

// ---------------------------------------------------------------------------
// PTX helpers (baseline ISA)
// ---------------------------------------------------------------------------
__device__ __forceinline__ uint32_t smem_u32(const void* p) {
    uint32_t a;
    asm("{ .reg .u64 t; cvta.to.shared.u64 t, %1; cvt.u32.u64 %0, t; }"
        : "=r"(a) : "l"(p));
    return a;
}
__device__ __forceinline__ void ldsm4(uint32_t* r, uint32_t a) {
    asm volatile("ldmatrix.sync.aligned.m8n8.x4.shared.b16 {%0,%1,%2,%3}, [%4];"
        : "=r"(r[0]), "=r"(r[1]), "=r"(r[2]), "=r"(r[3]) : "r"(a));
}
__device__ __forceinline__ void mma_f16(float* d, const uint32_t* a, const uint32_t* b) {
    asm volatile("mma.sync.aligned.m16n8k16.row.col.f32.f16.f16.f32 "
        "{%0,%1,%2,%3},{%4,%5,%6,%7},{%8,%9},{%0,%1,%2,%3};"
        : "+f"(d[0]), "+f"(d[1]), "+f"(d[2]), "+f"(d[3])
        : "r"(a[0]), "r"(a[1]), "r"(a[2]), "r"(a[3]), "r"(b[0]), "r"(b[1]));
}
__device__ __forceinline__ uint32_t cvt2h(float hi, float lo) {
    uint32_t r;
    asm("cvt.rn.f16x2.f32 %0, %1, %2;" : "=r"(r) : "f"(hi), "f"(lo));
    return r;
}
__device__ __forceinline__ uint32_t ex2h2(uint32_t x) {
    uint32_t r;
    asm("ex2.approx.f16x2 %0, %1;" : "=r"(r) : "r"(x));
    return r;
}
__device__ __forceinline__ void cpa16(uint32_t dst, const void* src) {
    asm volatile("cp.async.cg.shared.global [%0], [%1], 16;" :: "r"(dst), "l"(src));
}
#define CP_COMMIT() asm volatile("cp.async.commit_group;" ::: "memory")
#define CP_WAIT1()  asm volatile("cp.async.wait_group 1;" ::: "memory")
#define CP_WAIT0()  asm volatile("cp.async.wait_group 0;" ::: "memory")

// ---------------------------------------------------------------------------
// All weight splits in one kernel
// ---------------------------------------------------------------------------
__global__ __launch_bounds__(256)
void split_all(const float* __restrict__ Wt, const float* __restrict__ Wr,
               const float* __restrict__ Wo,
               __half* __restrict__ wth, __half* __restrict__ wtl,
               __half* __restrict__ wrh, __half* __restrict__ wrl,
               __half* __restrict__ wh,  __half* __restrict__ wl)
{
    int i = blockIdx.x * 256 + threadIdx.x;
    const float* src; __half *dh, *dl; int j;
    if (i < 8192)        { src = Wt; dh = wth; dl = wtl; j = i; }
    else if (i < 16384)  { src = Wr; dh = wrh; dl = wrl; j = i - 8192; }
    else                 { src = Wo; dh = wh;  dl = wl;  j = i - 16384; }
    float x = src[j];
    __half hh = __float2half_rn(x);
    dh[j] = hh;
    dl[j] = __float2half_rn(x - __half2float(hh));
}

// ---------------------------------------------------------------------------
// Convert V (= ref, [b][c][n]) to fp16
// ---------------------------------------------------------------------------
__global__ __launch_bounds__(256)
void conv_v(const float* __restrict__ ref, __half* __restrict__ vhi)
{
    size_t i = ((size_t)blockIdx.x * 256 + threadIdx.x) * 8;
    float4 a = *(const float4*)(ref + i);
    float4 b = *(const float4*)(ref + i + 4);
    float v[8] = {a.x, a.y, a.z, a.w, b.x, b.y, b.z, b.w};
    __align__(16) __half h[8];
#pragma unroll
    for (int j = 0; j < 8; j++) h[j] = __float2half_rn(v[j]);
    *(uint4*)(vhi + i) = *(const uint4*)h;
}

// ---------------------------------------------------------------------------
// Shared projection core for 128-thread CTAs, 64-token tiles.
// smem: WH[64][72], WL[64][72], TH[64][72], TL[64][72]  (36864 B)
// ---------------------------------------------------------------------------
#define PR_WH 0
#define PR_WL 9216
#define PR_TH 18432
#define PR_TL 27648
#define PR_SZ 36864

template<typename SM>
__device__ __forceinline__ void proj_half(
    SM* smc, uint32_t sb, int half,
    const float* __restrict__ xb,
    const __half* __restrict__ WH, const __half* __restrict__ WL,
    int tid, int wid, int lane, int rbase, float acc[8][4])
{
    const int lg  = lane >> 3, ln8 = lane & 7;
    const __half* whp = WH + half * 64;
    const __half* wlp = WL + half * 64;
    for (int i = tid; i < 512; i += 128) {
        int r = i >> 3, j = i & 7;
        *(uint4*)((char*)smc + PR_WH + r * 144 + j * 16) = *(const uint4*)(whp + r * 128 + j * 8);
        *(uint4*)((char*)smc + PR_WL + r * 144 + j * 16) = *(const uint4*)(wlp + r * 128 + j * 8);
    }
#pragma unroll
    for (int i = 0; i < 16; i++) {
        int tok = lane + 32 * (i & 1);
        int cp  = wid + 4 * (i >> 1);
        int c   = half * 64 + cp * 2;
        float x0 = xb[(size_t)c * NTOK + tok];
        float x1 = xb[(size_t)(c + 1) * NTOK + tok];
        __half h0 = __float2half_rn(x0), h1 = __float2half_rn(x1);
        __half l0 = __float2half_rn(x0 - __half2float(h0));
        __half l1 = __float2half_rn(x1 - __half2float(h1));
        *(__half2*)((char*)smc + PR_TH + tok * 144 + cp * 4) = __halves2half2(h0, h1);
        *(__half2*)((char*)smc + PR_TL + tok * 144 + cp * 4) = __halves2half2(l0, l1);
    }
    __syncthreads();

    uint32_t ah[4][4], al[4][4];
    {
        const int ar = rbase + (lane & 15);
        const int ac = 8 * (lane >> 4);
#pragma unroll
        for (int kk = 0; kk < 4; kk++) {
            uint32_t off = (uint32_t)(ar * RS + kk * 16 + ac) * 2;
            ldsm4(ah[kk], sb + PR_TH + off);
            ldsm4(al[kk], sb + PR_TL + off);
        }
    }
#pragma unroll
    for (int jn = 0; jn < 8; jn++) {
        uint32_t bh01[4], bh23[4], bl01[4], bl23[4];
        uint32_t wa = sb + PR_WH + (uint32_t)((jn * 8 + ln8) * RS + lg * 8) * 2;
        ldsm4(bh01, wa);
        ldsm4(bh23, wa + 64);
        ldsm4(bl01, wa + (PR_WL - PR_WH));
        ldsm4(bl23, wa + (PR_WL - PR_WH) + 64);
        mma_f16(acc[jn], ah[0], bh01);  mma_f16(acc[jn], ah[1], bh01 + 2);
        mma_f16(acc[jn], ah[2], bh23);  mma_f16(acc[jn], ah[3], bh23 + 2);
        mma_f16(acc[jn], ah[0], bl01);  mma_f16(acc[jn], ah[1], bl01 + 2);
        mma_f16(acc[jn], ah[2], bl23);  mma_f16(acc[jn], ah[3], bl23 + 2);
        mma_f16(acc[jn], al[0], bh01);  mma_f16(acc[jn], al[1], bh01 + 2);
        mma_f16(acc[jn], al[2], bh23);  mma_f16(acc[jn], al[3], bh23 + 2);
    }
    __syncthreads();
}

// ---------------------------------------------------------------------------
// K projection (tensor-core), 128 threads / 64 tokens, token-major output
// ---------------------------------------------------------------------------
__global__ __launch_bounds__(128)
void proj_k_tc(const float* __restrict__ ref,
               const __half* __restrict__ WrH, const __half* __restrict__ WrL,
               const float* __restrict__ b_ref,
               __half* __restrict__ khi, __half* __restrict__ klo)
{
    extern __shared__ __align__(16) char smk[];
    const uint32_t sb = smem_u32(smk);
    const int tid = threadIdx.x, wid = tid >> 5, lane = tid & 31;
    const int b = blockIdx.y, n0 = blockIdx.x * 64;
    const int rbase = wid * 16;
    const int col0 = 2 * (lane & 3);

    float acc[8][4];
#pragma unroll
    for (int jn = 0; jn < 8; jn++) {
        float2 bb = *(const float2*)&b_ref[jn * 8 + col0];
        acc[jn][0] = bb.x; acc[jn][1] = bb.y;
        acc[jn][2] = bb.x; acc[jn][3] = bb.y;
    }
    const float* xb = ref + (size_t)b * C * NTOK + n0;
#pragma unroll 1
    for (int half = 0; half < 2; half++)
        proj_half(smk, sb, half, xb, WrH, WrL, tid, wid, lane, rbase, acc);

    const int r0 = rbase + (lane >> 2);
#pragma unroll
    for (int jn = 0; jn < 8; jn++) {
        int col = jn * 8 + col0;
        float v0 = fmaxf(acc[jn][0], 0.f), v1 = fmaxf(acc[jn][1], 0.f);
        float v2 = fmaxf(acc[jn][2], 0.f), v3 = fmaxf(acc[jn][3], 0.f);
        __half h0 = __float2half_rn(v0), h1 = __float2half_rn(v1);
        __half h2 = __float2half_rn(v2), h3 = __float2half_rn(v3);
        size_t i0 = ((size_t)b * NTOK + n0 + r0) * CH + col;
        size_t i1 = ((size_t)b * NTOK + n0 + r0 + 8) * CH + col;
        *(__half2*)&khi[i0] = __halves2half2(h0, h1);
        *(__half2*)&khi[i1] = __halves2half2(h2, h3);
        *(__half2*)&klo[i0] = __halves2half2(__float2half_rn(v0 - __half2float(h0)),
                                             __float2half_rn(v1 - __half2float(h1)));
        *(__half2*)&klo[i1] = __halves2half2(__float2half_rn(v2 - __half2float(h2)),
                                             __float2half_rn(v3 - __half2float(h3)));
    }
}

// ---------------------------------------------------------------------------
// Flash attention: 128 threads (4 warps x 16 rows), 2 CTAs/SM (R10 config).
// QK is 2-term: Q (single fp16) x (Khi + Klo). AV 1-term + ones-MMA row sum.
// SMEM: 2 x { KH[64][72] KL[64][72] VH[128][72] } = 73728 B
// ---------------------------------------------------------------------------
#define OFF_KH 0
#define OFF_KL 9216
#define OFF_VH 18432
#define BUF    36864
#define SMEM_ATTN (2 * BUF)
#define EP_WH  0
#define EP_WL  18432
#define EP_TH  36864
#define EP_TL  46080

__global__ __launch_bounds__(128, 2)
void attn_mma(const __half* __restrict__ WtH, const __half* __restrict__ WtL,
              const float* __restrict__ b_tgt,
              const __half* __restrict__ Khi, const __half* __restrict__ Klo,
              const __half* __restrict__ Vhi,
              const __half* __restrict__ Wh,  const __half* __restrict__ Wl,
              const float* __restrict__ tgt,  const float* __restrict__ b_out,
              float* __restrict__ out)
{
    extern __shared__ __align__(16) char smc[];
    const uint32_t sb = smem_u32(smc);

    const int tid   = threadIdx.x;
    const int wid   = tid >> 5, lane = tid & 31;
    const int b     = blockIdx.y;
    const int n0    = blockIdx.x * TQ;
    const int rbase = wid * 16;
    const int lg    = lane >> 3;
    const int ln8   = lane & 7;
    const int lgr   = (lg >> 1) * 8 + ln8;
    const int lko   = 8 * (lg & 1);
    const int col0  = 2 * (lane & 3);

    const float* tb = tgt + (size_t)b * C * NTOK + n0;

    // ======== fused Q projection (fp16 output only, no lo split) ========
    uint32_t qa[4][4];
    {
        float qacc[8][4];
#pragma unroll
        for (int jn = 0; jn < 8; jn++) {
            float2 bb = *(const float2*)&b_tgt[jn * 8 + col0];
            qacc[jn][0] = bb.x; qacc[jn][1] = bb.y;
            qacc[jn][2] = bb.x; qacc[jn][3] = bb.y;
        }
#pragma unroll 1
        for (int half = 0; half < 2; half++)
            proj_half(smc, sb, half, tb, WtH, WtL, tid, wid, lane, rbase, qacc);

#pragma unroll
        for (int kk = 0; kk < 4; kk++) {
#pragma unroll
            for (int hh = 0; hh < 2; hh++) {
                int j = 2 * kk + hh;
                float v0 = fmaxf(qacc[j][0], 0.f), v1 = fmaxf(qacc[j][1], 0.f);
                float v2 = fmaxf(qacc[j][2], 0.f), v3 = fmaxf(qacc[j][3], 0.f);
                qa[kk][2 * hh]     = cvt2h(v1, v0);
                qa[kk][2 * hh + 1] = cvt2h(v3, v2);
            }
        }
    }

    // ======== main loop ========
    const __half* KHb = Khi + (size_t)b * NTOK * CH;
    const __half* KLb = Klo + (size_t)b * NTOK * CH;
    const __half* VHb = Vhi + (size_t)b * C * NTOK;
    auto prefetch = [&](int t, int bsel) {
        uint32_t base = sb + (uint32_t)bsel * BUF;
        const __half* khp = KHb + (size_t)t * TK * CH;
        const __half* klp = KLb + (size_t)t * TK * CH;
        for (int i = tid; i < 512; i += 128) {
            int r = i >> 3, j = i & 7;
            uint32_t d = base + r * 144 + j * 16;
            cpa16(d + OFF_KH, khp + r * 64 + j * 8);
            cpa16(d + OFF_KL, klp + r * 64 + j * 8);
        }
        const __half* vhp = VHb + t * TK;
        for (int i = tid; i < 1024; i += 128) {
            int c = i >> 3, j = i & 7;
            cpa16(base + OFF_VH + c * 144 + j * 16, vhp + (size_t)c * NTOK + j * 8);
        }
    };

    float o[16][4];
#pragma unroll
    for (int jn = 0; jn < 16; jn++)
#pragma unroll
        for (int e = 0; e < 4; e++) o[jn][e] = 0.0f;
    float osum[4] = {0.f, 0.f, 0.f, 0.f};
    float mx0 = -1e30f, mx1 = -1e30f;

    const uint32_t ones2[2] = {0x3C003C00u, 0x3C003C00u};
    const float L2E = 1.4426950408889634f;

    prefetch(0, 0);
    CP_COMMIT();

    for (int t = 0; t < KTILES; t++) {
        __syncthreads();
        if (t + 1 < KTILES) prefetch(t + 1, (t + 1) & 1);
        CP_COMMIT();
        CP_WAIT1();
        __syncthreads();
        const uint32_t base = sb + (uint32_t)(t & 1) * BUF;

        // ---- S = Q.(Khi + Klo), 2-term ----
        float s[8][4];
#pragma unroll
        for (int j = 0; j < 8; j++)
#pragma unroll
            for (int e = 0; e < 4; e++) s[j][e] = 0.0f;

#pragma unroll
        for (int kk = 0; kk < 4; kk++) {
#pragma unroll
            for (int jp = 0; jp < 4; jp++) {
                uint32_t kh4[4], kl4[4];
                uint32_t ka = base + OFF_KH +
                    (uint32_t)((jp * 16 + lgr) * RS + kk * 16 + lko) * 2;
                ldsm4(kh4, ka);
                ldsm4(kl4, ka + (OFF_KL - OFF_KH));
                mma_f16(s[2 * jp],     qa[kk], kh4);
                mma_f16(s[2 * jp + 1], qa[kk], kh4 + 2);
                mma_f16(s[2 * jp],     qa[kk], kl4);
                mma_f16(s[2 * jp + 1], qa[kk], kl4 + 2);
            }
        }

        // ---- online softmax (max + rescale) ----
        float a0 = -1e30f, a1 = -1e30f;
#pragma unroll
        for (int j = 0; j < 8; j++) {
            a0 = fmaxf(a0, fmaxf(s[j][0], s[j][1]));
            a1 = fmaxf(a1, fmaxf(s[j][2], s[j][3]));
        }
        a0 = fmaxf(a0, __shfl_xor_sync(0xffffffffu, a0, 1));
        a0 = fmaxf(a0, __shfl_xor_sync(0xffffffffu, a0, 2));
        a1 = fmaxf(a1, __shfl_xor_sync(0xffffffffu, a1, 1));
        a1 = fmaxf(a1, __shfl_xor_sync(0xffffffffu, a1, 2));
        float mn0 = fmaxf(mx0, a0), mn1 = fmaxf(mx1, a1);
        if (__any_sync(0xffffffffu, (mn0 > mx0) || (mn1 > mx1))) {
            float cr0 = __expf(mx0 - mn0), cr1 = __expf(mx1 - mn1);
#pragma unroll
            for (int jn = 0; jn < 16; jn++) {
                o[jn][0] *= cr0; o[jn][1] *= cr0;
                o[jn][2] *= cr1; o[jn][3] *= cr1;
            }
            osum[0] *= cr0; osum[1] *= cr0;
            osum[2] *= cr1; osum[3] *= cr1;
        }
        mx0 = mn0; mx1 = mn1;

        // ---- per-kk: exp then AV ----
        const float mL0 = mn0 * L2E, mL1 = mn1 * L2E;
#pragma unroll
        for (int kk = 0; kk < 4; kk++) {
            int j0 = 2 * kk, j1 = 2 * kk + 1;
            uint32_t ph[4];
            ph[0] = ex2h2(cvt2h(fmaf(s[j0][1], L2E, -mL0),
                                fmaf(s[j0][0], L2E, -mL0)));
            ph[1] = ex2h2(cvt2h(fmaf(s[j0][3], L2E, -mL1),
                                fmaf(s[j0][2], L2E, -mL1)));
            ph[2] = ex2h2(cvt2h(fmaf(s[j1][1], L2E, -mL0),
                                fmaf(s[j1][0], L2E, -mL0)));
            ph[3] = ex2h2(cvt2h(fmaf(s[j1][3], L2E, -mL1),
                                fmaf(s[j1][2], L2E, -mL1)));
            mma_f16(osum, ph, ones2);
#pragma unroll
            for (int jp = 0; jp < 8; jp++) {
                uint32_t vh4[4];
                uint32_t va = base + OFF_VH +
                    (uint32_t)((jp * 16 + lgr) * RS + kk * 16 + lko) * 2;
                ldsm4(vh4, va);
                mma_f16(o[2 * jp],     ph, vh4);
                mma_f16(o[2 * jp + 1], ph, vh4 + 2);
            }
        }
    }

    // ======== epilogue: fused gate GEMM (R10 layout) ========
    CP_WAIT0();
    __syncthreads();

    float g[16][4];
#pragma unroll
    for (int jn = 0; jn < 16; jn++) {
        float ba = b_out[jn * 8 + col0];
        float bb = b_out[jn * 8 + col0 + 1];
        g[jn][0] = ba; g[jn][1] = bb; g[jn][2] = ba; g[jn][3] = bb;
    }

#pragma unroll 1
    for (int half = 0; half < 2; half++) {
        const __half* whp = Wh + half * 64;
        const __half* wlp = Wl + half * 64;
        for (int i = tid; i < 1024; i += 128) {
            int r = i >> 3, j = i & 7;
            *(uint4*)(smc + EP_WH + r * 144 + j * 16) = *(const uint4*)(whp + r * 128 + j * 8);
            *(uint4*)(smc + EP_WL + r * 144 + j * 16) = *(const uint4*)(wlp + r * 128 + j * 8);
        }
        for (int i = 0; i < 16; i++) {
            int tok = lane + 32 * (i & 1);
            int cp  = wid + 4 * (i >> 1);
            int c   = half * 64 + cp * 2;
            float x0 = tb[(size_t)c * NTOK + tok];
            float x1 = tb[(size_t)(c + 1) * NTOK + tok];
            __half h0 = __float2half_rn(x0), h1 = __float2half_rn(x1);
            __half l0 = __float2half_rn(x0 - __half2float(h0));
            __half l1 = __float2half_rn(x1 - __half2float(h1));
            *(__half2*)(smc + EP_TH + tok * 144 + cp * 4) = __halves2half2(h0, h1);
            *(__half2*)(smc + EP_TL + tok * 144 + cp * 4) = __halves2half2(l0, l1);
        }
        __syncthreads();

        uint32_t ah[4][4], al[4][4];
        {
            const int ar = rbase + (lane & 15);
            const int ac = 8 * (lane >> 4);
#pragma unroll
            for (int kk = 0; kk < 4; kk++) {
                uint32_t off = (uint32_t)(ar * RS + kk * 16 + ac) * 2;
                ldsm4(ah[kk], sb + EP_TH + off);
                ldsm4(al[kk], sb + EP_TL + off);
            }
        }
#pragma unroll
        for (int jn = 0; jn < 16; jn++) {
            uint32_t bh01[4], bh23[4], bl01[4], bl23[4];
            uint32_t wa = sb + EP_WH + (uint32_t)((jn * 8 + ln8) * RS + lg * 8) * 2;
            ldsm4(bh01, wa);
            ldsm4(bh23, wa + 64);
            ldsm4(bl01, wa + (EP_WL - EP_WH));
            ldsm4(bl23, wa + (EP_WL - EP_WH) + 64);
            mma_f16(g[jn], ah[0], bh01);  mma_f16(g[jn], ah[1], bh01 + 2);
            mma_f16(g[jn], ah[2], bh23);  mma_f16(g[jn], ah[3], bh23 + 2);
            mma_f16(g[jn], ah[0], bl01);  mma_f16(g[jn], ah[1], bl01 + 2);
            mma_f16(g[jn], ah[2], bl23);  mma_f16(g[jn], ah[3], bl23 + 2);
            mma_f16(g[jn], al[0], bh01);  mma_f16(g[jn], al[1], bh01 + 2);
            mma_f16(g[jn], al[2], bh23);  mma_f16(g[jn], al[3], bh23 + 2);
        }
        __syncthreads();
    }

    // ---- normalize, gate, store ----
    const float inv0 = 1.0f / osum[0], inv1 = 1.0f / osum[2];
    const int tok = n0 + rbase + (lane >> 2);
#pragma unroll
    for (int jn = 0; jn < 16; jn++) {
        int c = jn * 8 + col0;
        size_t gi = ((size_t)b * C + c) * NTOK + tok;
        out[gi]            = o[jn][0] * inv0 * g[jn][0];
        out[gi + NTOK]     = o[jn][1] * inv0 * g[jn][1];
        out[gi + 8]        = o[jn][2] * inv1 * g[jn][2];
        out[gi + NTOK + 8] = o[jn][3] * inv1 * g[jn][3];
    }
}

// ---------------------------------------------------------------------------
extern "C" void kernel_launch(void* const* d_in, const int* in_sizes, int n_in,
                              void* d_out, int out_size)
{
    const float* tgt   = (const float*)d_in[0];
    const float* refp  = (const float*)d_in[1];
    const float* W_tgt = (const float*)d_in[2];
    const float* b_tgt = (const float*)d_in[3];
    const float* W_ref = (const float*)d_in[4];
    const float* b_ref = (const float*)d_in[5];
    const float* W_out = (const float*)d_in[6];
    const float* b_out = (const float*)d_in[7];
    float* out = (float*)d_out;

    __half *kh, *kl, *vh, *wh, *wl, *wth, *wtl, *wrh, *wrl;
    cudaGetSymbolAddress((void**)&kh,  g_Khi);
    cudaGetSymbolAddress((void**)&kl,  g_Klo);
    cudaGetSymbolAddress((void**)&vh,  g_Vhi);
    cudaGetSymbolAddress((void**)&wh,  g_Wh);
    cudaGetSymbolAddress((void**)&wl,  g_Wl);
    cudaGetSymbolAddress((void**)&wth, g_WtH);
    cudaGetSymbolAddress((void**)&wtl, g_WtL);
    cudaGetSymbolAddress((void**)&wrh, g_WrH);
    cudaGetSymbolAddress((void**)&wrl, g_WrL);

    cudaFuncSetAttribute(proj_k_tc, cudaFuncAttributeMaxDynamicSharedMemorySize, PR_SZ);
    cudaFuncSetAttribute(attn_mma,  cudaFuncAttributeMaxDynamicSharedMemorySize, SMEM_ATTN);

    split_all<<<(2 * CH * C + C * C) / 256, 256>>>(
        W_tgt, W_ref, W_out, wth, wtl, wrh, wrl, wh, wl);
    conv_v<<<(BS * C * NTOK) / (256 * 8), 256>>>(refp, vh);
    proj_k_tc<<<dim3(NTOK / 64, BS), 128, PR_SZ>>>(refp, wrh, wrl, b_ref, kh, kl);

    attn_mma<<<dim3(NTOK / TQ, BS), 128, SMEM_ATTN>>>(
        wth, wtl, b_tgt, kh, kl, vh, wh, wl, tgt, b_out, out);
}